// round 6
// baseline (speedup 1.0000x reference)
#include <cuda_runtime.h>
#include <cuda_bf16.h>
#include <cstdint>
#include <cstddef>

#define BATCH 16384
#define CLS   2048
#define NN    4096   // 2*CLS

// ---------------- GEMM config ----------------
#define BM 128
#define BN 128
#define BK 32
#define PITCH 40          // bf16 elems per smem row (32 data + 8 pad -> conflict-free ldmatrix)
#define STAGES 3
#define KTILES (BATCH / BK)   // 512
#define SMEM_STAGE_BYTES (2 * BM * PITCH * 2)   // A+B per stage = 20480
#define SMEM_BYTES (STAGES * SMEM_STAGE_BYTES)  // 61440

// ---------------- scratch (device globals: sanctioned workaround) ----------------
__device__ __align__(16) __nv_bfloat16 g_Xt[(size_t)NN * BATCH]; // 128MB, row r = column r of X, K-major
__device__ __align__(16) float g_G[(size_t)NN * NN];             // 64MB Gram matrix
__device__ float  g_colsum[NN];
__device__ float  g_sumsq[NN];
__device__ float  g_invn[NN];
__device__ double g_loss;

// ---------------- small helpers ----------------
__device__ __forceinline__ void cp_async16(void* smem_dst, const void* gsrc) {
    uint32_t s = (uint32_t)__cvta_generic_to_shared(smem_dst);
    asm volatile("cp.async.cg.shared.global [%0], [%1], 16;\n" :: "r"(s), "l"(gsrc));
}
__device__ __forceinline__ void cp_commit() {
    asm volatile("cp.async.commit_group;\n");
}
template <int N>
__device__ __forceinline__ void cp_wait() {
    asm volatile("cp.async.wait_group %0;\n" :: "n"(N));
}
__device__ __forceinline__ void ldsm4(uint32_t& r0, uint32_t& r1, uint32_t& r2, uint32_t& r3,
                                      uint32_t addr) {
    asm volatile("ldmatrix.sync.aligned.m8n8.x4.shared.b16 {%0,%1,%2,%3}, [%4];\n"
                 : "=r"(r0), "=r"(r1), "=r"(r2), "=r"(r3) : "r"(addr));
}
__device__ __forceinline__ void mma_bf16(float* c, const uint32_t* a, uint32_t b0, uint32_t b1) {
    asm volatile(
        "mma.sync.aligned.m16n8k16.row.col.f32.bf16.bf16.f32 "
        "{%0,%1,%2,%3}, {%4,%5,%6,%7}, {%8,%9}, {%0,%1,%2,%3};\n"
        : "+f"(c[0]), "+f"(c[1]), "+f"(c[2]), "+f"(c[3])
        : "r"(a[0]), "r"(a[1]), "r"(a[2]), "r"(a[3]), "r"(b0), "r"(b1));
}

// ---------------- K0: zero the accumulators (must run EVERY launch) ----------------
__global__ void k_zero() {
    int i = blockIdx.x * blockDim.x + threadIdx.x;
    if (i < NN) { g_colsum[i] = 0.f; g_sumsq[i] = 0.f; }
    if (i == 0) g_loss = 0.0;
}

// ---------------- K1: column sums + sums of squares (fp32 from original data) ----------------
__global__ void k_colstats(const float* __restrict__ qi, const float* __restrict__ qj) {
    int c = blockIdx.x * blockDim.x + threadIdx.x;   // 0..NN-1
    int seg = blockIdx.y;                             // 0..31
    const float* src = (c < CLS) ? (qi + c) : (qj + (c - CLS));
    const int seglen = BATCH / 32;
    int b0 = seg * seglen;
    float s = 0.f, s2 = 0.f;
#pragma unroll 8
    for (int b = b0; b < b0 + seglen; ++b) {
        float v = src[(size_t)b * CLS];
        s += v;
        s2 += v * v;
    }
    atomicAdd(&g_colsum[c], s);
    atomicAdd(&g_sumsq[c], s2);
}

// ---------------- K1b: inverse norms ----------------
__global__ void k_invn() {
    int i = blockIdx.x * blockDim.x + threadIdx.x;
    if (i < NN) g_invn[i] = rsqrtf(fmaxf(g_sumsq[i], 1e-30f));
}

// ---------------- K2: transpose + bf16 convert: Xt[r, b] ----------------
__global__ void k_transpose(const float* __restrict__ qi, const float* __restrict__ qj) {
    __shared__ float tile[32][33];
    int b0 = blockIdx.x * 32;
    int r0 = blockIdx.y * 32;
    const float* q = (r0 < CLS) ? qi : qj;
    int c0 = (r0 < CLS) ? r0 : (r0 - CLS);
    int tx = threadIdx.x, ty = threadIdx.y;
#pragma unroll
    for (int i = 0; i < 4; ++i) {
        int b = b0 + ty + i * 8;
        tile[ty + i * 8][tx] = q[(size_t)b * CLS + c0 + tx];
    }
    __syncthreads();
#pragma unroll
    for (int i = 0; i < 4; ++i) {
        int r = r0 + ty + i * 8;
        int b = b0 + tx;
        g_Xt[(size_t)r * BATCH + b] = __float2bfloat16(tile[tx][ty + i * 8]);
    }
}

// ---------------- K3: G = Xt * Xt^T (both operands K-major, bf16 MMA, fp32 acc) ----------------
__device__ __forceinline__ void gemm_issue_stage(__nv_bfloat16* smem, int stage, int kt,
                                                 const __nv_bfloat16* gA,
                                                 const __nv_bfloat16* gB, int tid) {
    __nv_bfloat16* sA = smem + stage * (2 * BM * PITCH);
    __nv_bfloat16* sB = sA + BM * PITCH;
#pragma unroll
    for (int i = 0; i < 4; ++i) {
        int c = tid + i * 256;       // 0..1023 ; 0..511 -> A, 512..1023 -> B
        int isB = c >> 9;
        int cc = c & 511;
        int m = cc >> 2;
        int k8 = (cc & 3) * 8;
        const __nv_bfloat16* src = (isB ? gB : gA) + (size_t)m * BATCH + kt + k8;
        __nv_bfloat16* dst = (isB ? sB : sA) + m * PITCH + k8;
        cp_async16(dst, src);
    }
    cp_commit();
}

__global__ void __launch_bounds__(256, 2) k_gemm() {
    extern __shared__ __align__(16) __nv_bfloat16 smem[];

    const int tid = threadIdx.x;
    const int lane = tid & 31;
    const int warp = tid >> 5;
    const int wm = warp >> 2;   // 0..1  (64 rows each)
    const int wn = warp & 3;    // 0..3  (32 cols each)
    const int bm0 = blockIdx.y * BM;
    const int bn0 = blockIdx.x * BN;

    const __nv_bfloat16* gA = g_Xt + (size_t)bm0 * BATCH;
    const __nv_bfloat16* gB = g_Xt + (size_t)bn0 * BATCH;

    float acc[4][4][4];
#pragma unroll
    for (int mt = 0; mt < 4; ++mt)
#pragma unroll
        for (int nt = 0; nt < 4; ++nt)
#pragma unroll
            for (int v = 0; v < 4; ++v) acc[mt][nt][v] = 0.f;

    // ldmatrix per-lane offsets (within the warp tile, K-major smem, pitch=PITCH)
    const int a_row = wm * 64 + (lane & 15);
    const int a_k   = (lane >> 4) * 8;
    const int b_row = wn * 32 + ((lane >> 4) & 1) * 8 + (lane & 7);
    const int b_k   = ((lane >> 3) & 1) * 8;

    // prologue
#pragma unroll
    for (int s = 0; s < STAGES - 1; ++s) gemm_issue_stage(smem, s, s * BK, gA, gB, tid);

    for (int it = 0; it < KTILES; ++it) {
        if (it + STAGES - 2 < KTILES) cp_wait<STAGES - 2>(); else cp_wait<0>();
        __syncthreads();

        const int stage = it % STAGES;
        const __nv_bfloat16* sA = smem + stage * (2 * BM * PITCH);
        const __nv_bfloat16* sB = sA + BM * PITCH;
        uint32_t aBase = (uint32_t)__cvta_generic_to_shared(sA);
        uint32_t bBase = (uint32_t)__cvta_generic_to_shared(sB);

#pragma unroll
        for (int ks = 0; ks < 2; ++ks) {   // two k16 steps per BK=32
            uint32_t a[4][4];
#pragma unroll
            for (int mt = 0; mt < 4; ++mt) {
                uint32_t addr = aBase + (uint32_t)(((a_row + mt * 16) * PITCH + ks * 16 + a_k) << 1);
                ldsm4(a[mt][0], a[mt][1], a[mt][2], a[mt][3], addr);
            }
            uint32_t b[2][4];
#pragma unroll
            for (int np = 0; np < 2; ++np) {
                uint32_t addr = bBase + (uint32_t)(((b_row + np * 16) * PITCH + ks * 16 + b_k) << 1);
                ldsm4(b[np][0], b[np][1], b[np][2], b[np][3], addr);
            }
#pragma unroll
            for (int mt = 0; mt < 4; ++mt)
#pragma unroll
                for (int nt = 0; nt < 4; ++nt)
                    mma_bf16(acc[mt][nt], a[mt], b[nt >> 1][(nt & 1) * 2], b[nt >> 1][(nt & 1) * 2 + 1]);
        }

        __syncthreads();
        if (it + STAGES - 1 < KTILES)
            gemm_issue_stage(smem, (it + STAGES - 1) % STAGES, (it + STAGES - 1) * BK, gA, gB, tid);
    }

    // epilogue: write G (fp32)
#pragma unroll
    for (int mt = 0; mt < 4; ++mt) {
        int row = bm0 + wm * 64 + mt * 16 + (lane >> 2);
#pragma unroll
        for (int nt = 0; nt < 4; ++nt) {
            int col = bn0 + wn * 32 + nt * 8 + (lane & 3) * 2;
            *(float2*)&g_G[(size_t)row * NN + col] = make_float2(acc[mt][nt][0], acc[mt][nt][1]);
            *(float2*)&g_G[(size_t)(row + 8) * NN + col] = make_float2(acc[mt][nt][2], acc[mt][nt][3]);
        }
    }
}

// ---------------- K4: per-row  log(sum_{s!=r} exp(sim)) - sim[r, partner] ----------------
__global__ void k_rowreduce() {
    __shared__ float sh[256];
    __shared__ float shpos;
    int r = blockIdx.x;
    float invr = g_invn[r];
    int partner = r ^ CLS;
    const float* row = g_G + (size_t)r * NN;
    float sum = 0.f;
    for (int s = threadIdx.x; s < NN; s += 256) {
        float sim = row[s] * invr * g_invn[s];
        if (s == partner) shpos = sim;
        if (s != r) sum += __expf(sim);
    }
    sh[threadIdx.x] = sum;
    __syncthreads();
#pragma unroll
    for (int off = 128; off > 0; off >>= 1) {
        if (threadIdx.x < off) sh[threadIdx.x] += sh[threadIdx.x + off];
        __syncthreads();
    }
    if (threadIdx.x == 0) {
        double l = (double)logf(sh[0]) - (double)shpos;
        atomicAdd(&g_loss, l);
    }
}

// ---------------- K5: entropy term + combine ----------------
__global__ void k_final(float* out) {
    __shared__ double sTi[256], sSi[256], sTj[256], sSj[256];
    int t = threadIdx.x;
    double Ti = 0, Si = 0, Tj = 0, Sj = 0;
    for (int c = t; c < CLS; c += 256) {
        double v = (double)g_colsum[c];
        Ti += v; Si += v * log(v);
        double w = (double)g_colsum[c + CLS];
        Tj += w; Sj += w * log(w);
    }
    sTi[t] = Ti; sSi[t] = Si; sTj[t] = Tj; sSj[t] = Sj;
    __syncthreads();
#pragma unroll
    for (int off = 128; off > 0; off >>= 1) {
        if (t < off) {
            sTi[t] += sTi[t + off]; sSi[t] += sSi[t + off];
            sTj[t] += sTj[t + off]; sSj[t] += sSj[t + off];
        }
        __syncthreads();
    }
    if (t == 0) {
        double nei = log((double)CLS) - log(sTi[0]) + sSi[0] / sTi[0];
        double nej = log((double)CLS) - log(sTj[0]) + sSj[0] / sTj[0];
        out[0] = (float)(g_loss / (double)NN + nei + nej);
    }
}

// ---------------- launch ----------------
extern "C" void kernel_launch(void* const* d_in, const int* in_sizes, int n_in,
                              void* d_out, int out_size) {
    const float* qi = (const float*)d_in[0];
    const float* qj = (const float*)d_in[1];
    float* out = (float*)d_out;

    // persistent per-function attribute; idempotent, non-stream op (safe under capture,
    // and it already took effect on the pre-capture correctness call)
    cudaFuncSetAttribute(k_gemm, cudaFuncAttributeMaxDynamicSharedMemorySize, SMEM_BYTES);

    k_zero<<<NN / 256, 256>>>();
    k_colstats<<<dim3(NN / 256, 32), 256>>>(qi, qj);
    k_transpose<<<dim3(BATCH / 32, NN / 32), dim3(32, 8)>>>(qi, qj);
    k_invn<<<NN / 256, 256>>>();
    k_gemm<<<dim3(NN / BN, NN / BM), 256, SMEM_BYTES>>>();
    k_rowreduce<<<NN, 256>>>();
    k_final<<<1, 256>>>(out);
}

// round 7
// speedup vs baseline: 1.6608x; 1.6608x over previous
#include <cuda_runtime.h>
#include <cuda_bf16.h>
#include <cstdint>
#include <cstddef>

#define BATCH 16384
#define CLS   2048
#define NN    4096   // 2*CLS

// ---------------- GEMM config ----------------
#define BM 128
#define BN 128
#define BK 32
#define PITCH 40          // bf16 elems per smem row (32 data + 8 pad -> conflict-free ldmatrix)
#define STAGES 3
#define KTILES (BATCH / BK)   // 512
#define SMEM_STAGE_BYTES (2 * BM * PITCH * 2)   // A+B per stage = 20480
#define SMEM_BYTES (STAGES * SMEM_STAGE_BYTES)  // 61440
#define NTILES_1D (NN / BM)                     // 32
#define NTRI (NTILES_1D * (NTILES_1D + 1) / 2)  // 528 upper-triangular tiles

// ---------------- scratch (device globals: sanctioned workaround) ----------------
__device__ __align__(16) __nv_bfloat16 g_Xt[(size_t)NN * BATCH]; // 128MB, row r = column r of X, K-major
__device__ __align__(16) float g_G[(size_t)NN * NN];             // 64MB Gram matrix
__device__ float  g_colsum[NN];
__device__ float  g_sumsq[NN];
__device__ float  g_invn[NN];
__device__ double g_loss;

// ---------------- small helpers ----------------
__device__ __forceinline__ void cp_async16(void* smem_dst, const void* gsrc) {
    uint32_t s = (uint32_t)__cvta_generic_to_shared(smem_dst);
    asm volatile("cp.async.cg.shared.global [%0], [%1], 16;\n" :: "r"(s), "l"(gsrc));
}
__device__ __forceinline__ void cp_commit() {
    asm volatile("cp.async.commit_group;\n");
}
template <int N>
__device__ __forceinline__ void cp_wait() {
    asm volatile("cp.async.wait_group %0;\n" :: "n"(N));
}
__device__ __forceinline__ void ldsm4(uint32_t& r0, uint32_t& r1, uint32_t& r2, uint32_t& r3,
                                      uint32_t addr) {
    asm volatile("ldmatrix.sync.aligned.m8n8.x4.shared.b16 {%0,%1,%2,%3}, [%4];\n"
                 : "=r"(r0), "=r"(r1), "=r"(r2), "=r"(r3) : "r"(addr));
}
__device__ __forceinline__ void mma_bf16(float* c, const uint32_t* a, uint32_t b0, uint32_t b1) {
    asm volatile(
        "mma.sync.aligned.m16n8k16.row.col.f32.bf16.bf16.f32 "
        "{%0,%1,%2,%3}, {%4,%5,%6,%7}, {%8,%9}, {%0,%1,%2,%3};\n"
        : "+f"(c[0]), "+f"(c[1]), "+f"(c[2]), "+f"(c[3])
        : "r"(a[0]), "r"(a[1]), "r"(a[2]), "r"(a[3]), "r"(b0), "r"(b1));
}

// ---------------- K0: zero the accumulators (must run EVERY launch) ----------------
__global__ void k_zero() {
    int i = blockIdx.x * blockDim.x + threadIdx.x;
    if (i < NN) { g_colsum[i] = 0.f; g_sumsq[i] = 0.f; }
    if (i == 0) g_loss = 0.0;
}

// ---------------- K1b: inverse norms ----------------
__global__ void k_invn() {
    int i = blockIdx.x * blockDim.x + threadIdx.x;
    if (i < NN) g_invn[i] = rsqrtf(fmaxf(g_sumsq[i], 1e-30f));
}

// ---------------- K2: transpose + bf16 convert + fused column stats ----------------
// Xt[r, b] = X[b, r] as bf16; also accumulates per-column sum / sumsq in fp32.
__global__ void k_transpose(const float* __restrict__ qi, const float* __restrict__ qj) {
    __shared__ float tile[32][33];
    __shared__ float s_s[8][32];
    __shared__ float s_s2[8][32];
    int b0 = blockIdx.x * 32;
    int r0 = blockIdx.y * 32;
    const float* q = (r0 < CLS) ? qi : qj;
    int c0 = (r0 < CLS) ? r0 : (r0 - CLS);
    int tx = threadIdx.x, ty = threadIdx.y;

    float s = 0.f, s2 = 0.f;
#pragma unroll
    for (int i = 0; i < 4; ++i) {
        int b = b0 + ty + i * 8;
        float v = q[(size_t)b * CLS + c0 + tx];
        tile[ty + i * 8][tx] = v;
        s += v;
        s2 += v * v;
    }
    s_s[ty][tx] = s;
    s_s2[ty][tx] = s2;
    __syncthreads();
#pragma unroll
    for (int i = 0; i < 4; ++i) {
        int r = r0 + ty + i * 8;
        int b = b0 + tx;
        g_Xt[(size_t)r * BATCH + b] = __float2bfloat16(tile[tx][ty + i * 8]);
    }
    if (ty == 0) {
        float ts = 0.f, ts2 = 0.f;
#pragma unroll
        for (int w = 0; w < 8; ++w) { ts += s_s[w][tx]; ts2 += s_s2[w][tx]; }
        atomicAdd(&g_colsum[r0 + tx], ts);
        atomicAdd(&g_sumsq[r0 + tx], ts2);
    }
}

// ---------------- K3: G = Xt * Xt^T, upper-triangular block tiles only ----------------
__device__ __forceinline__ void gemm_issue_stage(__nv_bfloat16* smem, int stage, int kt,
                                                 const __nv_bfloat16* gA,
                                                 const __nv_bfloat16* gB, int tid) {
    __nv_bfloat16* sA = smem + stage * (2 * BM * PITCH);
    __nv_bfloat16* sB = sA + BM * PITCH;
#pragma unroll
    for (int i = 0; i < 4; ++i) {
        int c = tid + i * 256;       // 0..1023 ; 0..511 -> A, 512..1023 -> B
        int isB = c >> 9;
        int cc = c & 511;
        int m = cc >> 2;
        int k8 = (cc & 3) * 8;
        const __nv_bfloat16* src = (isB ? gB : gA) + (size_t)m * BATCH + kt + k8;
        __nv_bfloat16* dst = (isB ? sB : sA) + m * PITCH + k8;
        cp_async16(dst, src);
    }
    cp_commit();
}

__global__ void __launch_bounds__(256, 2) k_gemm() {
    extern __shared__ __align__(16) __nv_bfloat16 smem[];

    const int tid = threadIdx.x;
    const int lane = tid & 31;
    const int warp = tid >> 5;
    const int wm = warp >> 2;   // 0..1  (64 rows each)
    const int wn = warp & 3;    // 0..3  (32 cols each)

    // ---- triangular tile decode: t -> (bi <= bj) ----
    int t = blockIdx.x;
    int u = (NTRI - 1) - t;
    int k = (int)((sqrtf((float)(8 * u + 1)) - 1.0f) * 0.5f);
    while (k * (k + 1) / 2 > u) --k;
    while ((k + 1) * (k + 2) / 2 <= u) ++k;
    int bi = (NTILES_1D - 1) - k;
    int bj = (NTILES_1D - 1) - (u - k * (k + 1) / 2);
    const int bm0 = bi * BM;
    const int bn0 = bj * BN;
    const bool diag = (bi == bj);

    const __nv_bfloat16* gA = g_Xt + (size_t)bm0 * BATCH;
    const __nv_bfloat16* gB = g_Xt + (size_t)bn0 * BATCH;

    float acc[4][4][4];
#pragma unroll
    for (int mt = 0; mt < 4; ++mt)
#pragma unroll
        for (int nt = 0; nt < 4; ++nt)
#pragma unroll
            for (int v = 0; v < 4; ++v) acc[mt][nt][v] = 0.f;

    // ldmatrix per-lane offsets (within the warp tile, K-major smem, pitch=PITCH)
    const int a_row = wm * 64 + (lane & 15);
    const int a_k   = (lane >> 4) * 8;
    const int b_row = wn * 32 + ((lane >> 4) & 1) * 8 + (lane & 7);
    const int b_k   = ((lane >> 3) & 1) * 8;

    // prologue
#pragma unroll
    for (int s = 0; s < STAGES - 1; ++s) gemm_issue_stage(smem, s, s * BK, gA, gB, tid);

    for (int it = 0; it < KTILES; ++it) {
        if (it + STAGES - 2 < KTILES) cp_wait<STAGES - 2>(); else cp_wait<0>();
        __syncthreads();

        const int stage = it % STAGES;
        const __nv_bfloat16* sA = smem + stage * (2 * BM * PITCH);
        const __nv_bfloat16* sB = sA + BM * PITCH;
        uint32_t aBase = (uint32_t)__cvta_generic_to_shared(sA);
        uint32_t bBase = (uint32_t)__cvta_generic_to_shared(sB);

#pragma unroll
        for (int ks = 0; ks < 2; ++ks) {   // two k16 steps per BK=32
            uint32_t a[4][4];
#pragma unroll
            for (int mt = 0; mt < 4; ++mt) {
                uint32_t addr = aBase + (uint32_t)(((a_row + mt * 16) * PITCH + ks * 16 + a_k) << 1);
                ldsm4(a[mt][0], a[mt][1], a[mt][2], a[mt][3], addr);
            }
            uint32_t b[2][4];
#pragma unroll
            for (int np = 0; np < 2; ++np) {
                uint32_t addr = bBase + (uint32_t)(((b_row + np * 16) * PITCH + ks * 16 + b_k) << 1);
                ldsm4(b[np][0], b[np][1], b[np][2], b[np][3], addr);
            }
#pragma unroll
            for (int mt = 0; mt < 4; ++mt)
#pragma unroll
                for (int nt = 0; nt < 4; ++nt)
                    mma_bf16(acc[mt][nt], a[mt], b[nt >> 1][(nt & 1) * 2], b[nt >> 1][(nt & 1) * 2 + 1]);
        }

        __syncthreads();
        if (it + STAGES - 1 < KTILES)
            gemm_issue_stage(smem, (it + STAGES - 1) % STAGES, (it + STAGES - 1) * BK, gA, gB, tid);
    }

    // epilogue: write G tile; mirror transposed copy for off-diagonal tiles
#pragma unroll
    for (int mt = 0; mt < 4; ++mt) {
        int row = bm0 + wm * 64 + mt * 16 + (lane >> 2);
#pragma unroll
        for (int nt = 0; nt < 4; ++nt) {
            int col = bn0 + wn * 32 + nt * 8 + (lane & 3) * 2;
            *(float2*)&g_G[(size_t)row * NN + col] = make_float2(acc[mt][nt][0], acc[mt][nt][1]);
            *(float2*)&g_G[(size_t)(row + 8) * NN + col] = make_float2(acc[mt][nt][2], acc[mt][nt][3]);
            if (!diag) {
                g_G[(size_t)col * NN + row]           = acc[mt][nt][0];
                g_G[(size_t)(col + 1) * NN + row]     = acc[mt][nt][1];
                g_G[(size_t)col * NN + row + 8]       = acc[mt][nt][2];
                g_G[(size_t)(col + 1) * NN + row + 8] = acc[mt][nt][3];
            }
        }
    }
}

// ---------------- K4: per-row  log(sum_{s!=r} exp(sim)) - sim[r, partner] ----------------
__global__ void k_rowreduce() {
    __shared__ float sh[256];
    __shared__ float shpos;
    int r = blockIdx.x;
    float invr = g_invn[r];
    int partner = r ^ CLS;
    const float* row = g_G + (size_t)r * NN;
    float sum = 0.f;
    for (int s = threadIdx.x; s < NN; s += 256) {
        float sim = row[s] * invr * g_invn[s];
        if (s == partner) shpos = sim;
        if (s != r) sum += __expf(sim);
    }
    sh[threadIdx.x] = sum;
    __syncthreads();
#pragma unroll
    for (int off = 128; off > 0; off >>= 1) {
        if (threadIdx.x < off) sh[threadIdx.x] += sh[threadIdx.x + off];
        __syncthreads();
    }
    if (threadIdx.x == 0) {
        double l = (double)logf(sh[0]) - (double)shpos;
        atomicAdd(&g_loss, l);
    }
}

// ---------------- K5: entropy term + combine ----------------
__global__ void k_final(float* out) {
    __shared__ double sTi[256], sSi[256], sTj[256], sSj[256];
    int t = threadIdx.x;
    double Ti = 0, Si = 0, Tj = 0, Sj = 0;
    for (int c = t; c < CLS; c += 256) {
        double v = (double)g_colsum[c];
        Ti += v; Si += v * log(v);
        double w = (double)g_colsum[c + CLS];
        Tj += w; Sj += w * log(w);
    }
    sTi[t] = Ti; sSi[t] = Si; sTj[t] = Tj; sSj[t] = Sj;
    __syncthreads();
#pragma unroll
    for (int off = 128; off > 0; off >>= 1) {
        if (t < off) {
            sTi[t] += sTi[t + off]; sSi[t] += sSi[t + off];
            sTj[t] += sTj[t + off]; sSj[t] += sSj[t + off];
        }
        __syncthreads();
    }
    if (t == 0) {
        double nei = log((double)CLS) - log(sTi[0]) + sSi[0] / sTi[0];
        double nej = log((double)CLS) - log(sTj[0]) + sSj[0] / sTj[0];
        out[0] = (float)(g_loss / (double)NN + nei + nej);
    }
}

// ---------------- launch ----------------
extern "C" void kernel_launch(void* const* d_in, const int* in_sizes, int n_in,
                              void* d_out, int out_size) {
    const float* qi = (const float*)d_in[0];
    const float* qj = (const float*)d_in[1];
    float* out = (float*)d_out;

    cudaFuncSetAttribute(k_gemm, cudaFuncAttributeMaxDynamicSharedMemorySize, SMEM_BYTES);

    k_zero<<<NN / 256, 256>>>();
    k_transpose<<<dim3(BATCH / 32, NN / 32), dim3(32, 8)>>>(qi, qj);
    k_invn<<<NN / 256, 256>>>();
    k_gemm<<<NTRI, 256, SMEM_BYTES>>>();
    k_rowreduce<<<NN, 256>>>();
    k_final<<<1, 256>>>(out);
}

// round 9
// speedup vs baseline: 1.9220x; 1.1573x over previous
#include <cuda_runtime.h>
#include <cuda_bf16.h>
#include <cuda_fp8.h>
#include <cstdint>
#include <cstddef>

#define BATCH 16384
#define CLS   2048
#define NN    4096   // 2*CLS

// ---------------- FP8 GEMM config ----------------
#define TM 128
#define TN 128
#define BK 64                  // fp8 elems per stage row (64 bytes)
#define PITCHB 80              // bytes per smem row (64 data + 16 pad, conflict-free ldmatrix)
#define STAGES 4
#define NITER (BATCH / BK)     // 256
#define A_STAGE (TM * PITCHB)  // 10240 bytes
#define STAGE_BYTES (2 * A_STAGE)            // 20480
#define SMEM_BYTES (STAGES * STAGE_BYTES)    // 81920
#define NT1D (NN / TM)                        // 32
#define NTRI (NT1D * (NT1D + 1) / 2)          // 528 upper-triangular tiles

// ---------------- scratch (device globals) ----------------
__device__ __align__(16) uint8_t g_Xf[(size_t)NN * BATCH];  // 64MB, K-major e4m3
__device__ float g_colsum[NN];
__device__ float g_sumsq[NN];
__device__ float g_invn[NN];
__device__ float g_rowsum[NN];   // sum_{s!=r} exp(sim[r,s])
__device__ float g_pos[NN];      // sim[r, r^CLS]

// ---------------- helpers ----------------
__device__ __forceinline__ uint32_t smem_u32(const void* p) {
    uint32_t a;
    asm("{ .reg .u64 t; cvta.to.shared.u64 t, %1; cvt.u32.u64 %0, t; }" : "=r"(a) : "l"(p));
    return a;
}
__device__ __forceinline__ void cp_async16s(uint32_t dst, const void* src) {
    asm volatile("cp.async.cg.shared.global [%0], [%1], 16;\n" :: "r"(dst), "l"(src));
}
__device__ __forceinline__ void cp_commit() { asm volatile("cp.async.commit_group;\n"); }
template <int N>
__device__ __forceinline__ void cp_wait() { asm volatile("cp.async.wait_group %0;\n" :: "n"(N)); }

__device__ __forceinline__ void ldsm4(uint32_t& r0, uint32_t& r1, uint32_t& r2, uint32_t& r3,
                                      uint32_t addr) {
    asm volatile("ldmatrix.sync.aligned.m8n8.x4.shared.b16 {%0,%1,%2,%3}, [%4];\n"
                 : "=r"(r0), "=r"(r1), "=r"(r2), "=r"(r3) : "r"(addr));
}
// fp8 e4m3 mma: m16n8k32, fp32 accum
__device__ __forceinline__ void mma_fp8(float* c, const uint32_t* a, uint32_t b0, uint32_t b1) {
    asm volatile(
        "mma.sync.aligned.m16n8k32.row.col.f32.e4m3.e4m3.f32 "
        "{%0,%1,%2,%3}, {%4,%5,%6,%7}, {%8,%9}, {%0,%1,%2,%3};\n"
        : "+f"(c[0]), "+f"(c[1]), "+f"(c[2]), "+f"(c[3])
        : "r"(a[0]), "r"(a[1]), "r"(a[2]), "r"(a[3]), "r"(b0), "r"(b1));
}

// ---------------- K0: zero accumulators (every launch) ----------------
__global__ void k_zero() {
    int i = blockIdx.x * blockDim.x + threadIdx.x;
    if (i < NN) { g_colsum[i] = 0.f; g_sumsq[i] = 0.f; g_rowsum[i] = 0.f; }
}

// ---------------- K1b: inverse norms (fp32, from original data) ----------------
__global__ void k_invn() {
    int i = blockIdx.x * blockDim.x + threadIdx.x;
    if (i < NN) g_invn[i] = rsqrtf(fmaxf(g_sumsq[i], 1e-30f));
}

// ---------------- K2: transpose + e4m3 convert + fused column stats ----------------
__global__ void k_transpose(const float* __restrict__ qi, const float* __restrict__ qj) {
    __shared__ float tile[32][33];
    __shared__ float s_s[8][32];
    __shared__ float s_s2[8][32];
    int b0 = blockIdx.x * 32;
    int r0 = blockIdx.y * 32;
    const float* q = (r0 < CLS) ? qi : qj;
    int c0 = (r0 < CLS) ? r0 : (r0 - CLS);
    int tx = threadIdx.x, ty = threadIdx.y;

    float s = 0.f, s2 = 0.f;
#pragma unroll
    for (int i = 0; i < 4; ++i) {
        int b = b0 + ty + i * 8;
        float v = q[(size_t)b * CLS + c0 + tx];
        tile[ty + i * 8][tx] = v;
        s += v; s2 += v * v;
    }
    s_s[ty][tx] = s;
    s_s2[ty][tx] = s2;
    __syncthreads();
#pragma unroll
    for (int i = 0; i < 4; ++i) {
        int r = r0 + ty + i * 8;
        int b = b0 + tx;
        g_Xf[(size_t)r * BATCH + b] =
            __nv_cvt_float_to_fp8(tile[tx][ty + i * 8], __NV_SATFINITE, __NV_E4M3);
    }
    if (ty == 0) {
        float ts = 0.f, ts2 = 0.f;
#pragma unroll
        for (int w = 0; w < 8; ++w) { ts += s_s[w][tx]; ts2 += s_s2[w][tx]; }
        atomicAdd(&g_colsum[r0 + tx], ts);
        atomicAdd(&g_sumsq[r0 + tx], ts2);
    }
}

// ---------------- K3: fp8 GEMM, triangular tiles, fused exp/rowsum epilogue ----------------
__device__ __forceinline__ void issue_stage(uint32_t smem_base, int stage, int k0,
                                            int M0, int C0, int tid) {
    uint32_t sbase = smem_base + stage * STAGE_BYTES;
#pragma unroll
    for (int i = 0; i < 8; ++i) {
        int c = i * 128 + tid;      // 0..1023 chunks of 16B; 0..511 -> A, rest -> B
        int isB = c >> 9;
        int cc = c & 511;
        int row = cc >> 2;
        int j = cc & 3;
        const uint8_t* src = g_Xf + (size_t)((isB ? C0 : M0) + row) * BATCH + k0 + j * 16;
        uint32_t dst = sbase + (isB ? (uint32_t)A_STAGE : 0u) + row * PITCHB + j * 16;
        cp_async16s(dst, src);
    }
    cp_commit();
}

__global__ void __launch_bounds__(128, 2) k_gemm() {
    extern __shared__ __align__(128) uint8_t smem[];
    const uint32_t smem_base = smem_u32(smem);
    const int tid = threadIdx.x;
    const int lane = tid & 31;
    const int warp = tid >> 5;
    const int wm = warp >> 1;   // 0..1 (64 rows)
    const int wn = warp & 1;    // 0..1 (64 cols)

    // triangular tile decode: blockIdx.x -> (bi <= bj)
    int t = blockIdx.x;
    int u = (NTRI - 1) - t;
    int k = (int)((sqrtf((float)(8 * u + 1)) - 1.0f) * 0.5f);
    while (k * (k + 1) / 2 > u) --k;
    while ((k + 1) * (k + 2) / 2 <= u) ++k;
    const int bi = (NT1D - 1) - k;
    const int bj = (NT1D - 1) - (u - k * (k + 1) / 2);
    const int M0 = bi * TM;
    const int C0 = bj * TN;
    const bool diag = (bi == bj);
    const bool ptile = (bj == bi + (CLS / TM));   // partner-diagonal block

    float acc[4][8][4];
#pragma unroll
    for (int mt = 0; mt < 4; ++mt)
#pragma unroll
        for (int nt = 0; nt < 8; ++nt)
#pragma unroll
            for (int v = 0; v < 4; ++v) acc[mt][nt][v] = 0.f;

    // per-lane ldmatrix offsets (byte units within PITCHB rows)
    const int a_row  = wm * 64 + (lane & 15);
    const int a_byte = (lane >> 4) * 16;
    const int b_rowb = wn * 64 + ((lane >> 4) & 1) * 8 + (lane & 7);
    const int b_byte = ((lane >> 3) & 1) * 16;

    // prologue
#pragma unroll
    for (int s = 0; s < STAGES - 1; ++s) issue_stage(smem_base, s, s * BK, M0, C0, tid);

    for (int it = 0; it < NITER; ++it) {
        if (it + STAGES - 1 <= NITER) cp_wait<STAGES - 2>(); else cp_wait<0>();
        __syncthreads();

        const uint32_t aB = smem_base + (it % STAGES) * STAGE_BYTES;
        const uint32_t bB = aB + A_STAGE;

#pragma unroll
        for (int ks = 0; ks < 2; ++ks) {     // two K=32 steps per BK=64
            uint32_t a[4][4];
#pragma unroll
            for (int mt = 0; mt < 4; ++mt)
                ldsm4(a[mt][0], a[mt][1], a[mt][2], a[mt][3],
                      aB + (uint32_t)((a_row + mt * 16) * PITCHB + ks * 32 + a_byte));
            uint32_t b[4][4];
#pragma unroll
            for (int i = 0; i < 4; ++i)
                ldsm4(b[i][0], b[i][1], b[i][2], b[i][3],
                      bB + (uint32_t)((b_rowb + i * 16) * PITCHB + ks * 32 + b_byte));
#pragma unroll
            for (int mt = 0; mt < 4; ++mt)
#pragma unroll
                for (int nt = 0; nt < 8; ++nt)
                    mma_fp8(acc[mt][nt], a[mt],
                            b[nt >> 1][(nt & 1) * 2], b[nt >> 1][(nt & 1) * 2 + 1]);
        }

        __syncthreads();
        const int pf = it + STAGES - 1;
        if (pf < NITER) issue_stage(smem_base, pf % STAGES, pf * BK, M0, C0, tid);
    }

    // ---------- fused epilogue ----------
    __syncthreads();
    float* s_inv = (float*)smem;      // [0..127]=row invn, [128..255]=col invn
    s_inv[tid] = g_invn[M0 + tid];
    s_inv[128 + tid] = g_invn[C0 + tid];
    __syncthreads();

    const int r_loc0 = wm * 64 + (lane >> 2);
    const int c_loc0 = wn * 64 + (lane & 3) * 2;
    float csum[8][2];
#pragma unroll
    for (int nt = 0; nt < 8; ++nt) { csum[nt][0] = 0.f; csum[nt][1] = 0.f; }

#pragma unroll
    for (int mt = 0; mt < 4; ++mt) {
        const int rA = r_loc0 + mt * 16;
        const int rB = rA + 8;
        const float invA = s_inv[rA], invB = s_inv[rB];
        float sA = 0.f, sB = 0.f;
#pragma unroll
        for (int nt = 0; nt < 8; ++nt) {
            const int c0l = c_loc0 + nt * 8;
            const float ic0 = s_inv[128 + c0l], ic1 = s_inv[128 + c0l + 1];
            const float simA0 = acc[mt][nt][0] * invA * ic0;
            const float simA1 = acc[mt][nt][1] * invA * ic1;
            const float simB0 = acc[mt][nt][2] * invB * ic0;
            const float simB1 = acc[mt][nt][3] * invB * ic1;
            if (ptile) {   // partner: global col == global row + CLS  <=> same local idx
                if (rA == c0l)     { g_pos[M0 + rA] = simA0; g_pos[C0 + c0l] = simA0; }
                if (rA == c0l + 1) { g_pos[M0 + rA] = simA1; g_pos[C0 + c0l + 1] = simA1; }
                if (rB == c0l)     { g_pos[M0 + rB] = simB0; g_pos[C0 + c0l] = simB0; }
                if (rB == c0l + 1) { g_pos[M0 + rB] = simB1; g_pos[C0 + c0l + 1] = simB1; }
            }
            float eA0 = __expf(simA0), eA1 = __expf(simA1);
            float eB0 = __expf(simB0), eB1 = __expf(simB1);
            if (diag) {   // exclude self
                if (rA == c0l)     eA0 = 0.f;
                if (rA == c0l + 1) eA1 = 0.f;
                if (rB == c0l)     eB0 = 0.f;
                if (rB == c0l + 1) eB1 = 0.f;
            }
            sA += eA0 + eA1;
            sB += eB0 + eB1;
            if (!diag) {   // symmetric: same values feed the transposed rows
                csum[nt][0] += eA0 + eB0;
                csum[nt][1] += eA1 + eB1;
            }
        }
        sA += __shfl_xor_sync(0xffffffffu, sA, 1);
        sA += __shfl_xor_sync(0xffffffffu, sA, 2);
        sB += __shfl_xor_sync(0xffffffffu, sB, 1);
        sB += __shfl_xor_sync(0xffffffffu, sB, 2);
        if ((lane & 3) == 0) {
            atomicAdd(&g_rowsum[M0 + rA], sA);
            atomicAdd(&g_rowsum[M0 + rB], sB);
        }
    }
    if (!diag) {
#pragma unroll
        for (int nt = 0; nt < 8; ++nt)
#pragma unroll
            for (int v = 0; v < 2; ++v) {
                float x = csum[nt][v];
                x += __shfl_xor_sync(0xffffffffu, x, 4);
                x += __shfl_xor_sync(0xffffffffu, x, 8);
                x += __shfl_xor_sync(0xffffffffu, x, 16);
                if (lane < 4)
                    atomicAdd(&g_rowsum[C0 + wn * 64 + nt * 8 + lane * 2 + v], x);
            }
    }
}

// ---------------- K5: entropy + ce combine ----------------
__global__ void k_final(float* out) {
    __shared__ double sC[256], sTi[256], sSi[256], sTj[256], sSj[256];
    int t = threadIdx.x;
    double ce = 0.0;
    for (int r = t; r < NN; r += 256)
        ce += (double)logf(g_rowsum[r]) - (double)g_pos[r];
    double Ti = 0, Si = 0, Tj = 0, Sj = 0;
    for (int c = t; c < CLS; c += 256) {
        double v = (double)g_colsum[c];
        Ti += v; Si += v * log(v);
        double w = (double)g_colsum[c + CLS];
        Tj += w; Sj += w * log(w);
    }
    sC[t] = ce; sTi[t] = Ti; sSi[t] = Si; sTj[t] = Tj; sSj[t] = Sj;
    __syncthreads();
#pragma unroll
    for (int off = 128; off > 0; off >>= 1) {
        if (t < off) {
            sC[t] += sC[t + off];
            sTi[t] += sTi[t + off]; sSi[t] += sSi[t + off];
            sTj[t] += sTj[t + off]; sSj[t] += sSj[t + off];
        }
        __syncthreads();
    }
    if (t == 0) {
        double nei = log((double)CLS) - log(sTi[0]) + sSi[0] / sTi[0];
        double nej = log((double)CLS) - log(sTj[0]) + sSj[0] / sTj[0];
        out[0] = (float)(sC[0] / (double)NN + nei + nej);
    }
}

// ---------------- launch ----------------
extern "C" void kernel_launch(void* const* d_in, const int* in_sizes, int n_in,
                              void* d_out, int out_size) {
    const float* qi = (const float*)d_in[0];
    const float* qj = (const float*)d_in[1];
    float* out = (float*)d_out;

    cudaFuncSetAttribute(k_gemm, cudaFuncAttributeMaxDynamicSharedMemorySize, SMEM_BYTES);

    k_zero<<<NN / 256, 256>>>();
    k_transpose<<<dim3(BATCH / 32, NN / 32), dim3(32, 8)>>>(qi, qj);
    k_invn<<<NN / 256, 256>>>();
    k_gemm<<<NTRI, 128, SMEM_BYTES>>>();
    k_final<<<1, 256>>>(out);
}

// round 10
// speedup vs baseline: 1.9453x; 1.0121x over previous
#include <cuda_runtime.h>
#include <cuda_bf16.h>
#include <cuda_fp8.h>
#include <cstdint>
#include <cstddef>

#define BATCH 16384
#define CLS   2048
#define NN    4096   // 2*CLS

// ---------------- FP8 GEMM config ----------------
#define TM 128
#define TN 128
#define BK 64                  // fp8 elems per stage row (64 bytes)
#define PITCHB 80              // bytes per smem row (64 data + 16 pad, conflict-free ldmatrix)
#define STAGES 4
#define NITER (BATCH / BK)     // 256
#define A_STAGE (TM * PITCHB)  // 10240 bytes
#define STAGE_BYTES (2 * A_STAGE)            // 20480
#define SMEM_BYTES (STAGES * STAGE_BYTES)    // 81920
#define NT1D (NN / TM)                        // 32
#define NTRI (NT1D * (NT1D + 1) / 2)          // 528 upper-triangular tiles

// ---------------- scratch (device globals) ----------------
__device__ __align__(16) uint8_t g_Xf[(size_t)NN * BATCH];  // 64MB, K-major e4m3
__device__ float g_colsum[NN];
__device__ float g_sumsq[NN];
__device__ float g_invn[NN];
__device__ float g_rowsum[NN];   // sum_{s!=r} exp(sim[r,s])
__device__ float g_pos[NN];      // sim[r, r^CLS]

// ---------------- helpers ----------------
__device__ __forceinline__ uint32_t smem_u32(const void* p) {
    uint32_t a;
    asm("{ .reg .u64 t; cvta.to.shared.u64 t, %1; cvt.u32.u64 %0, t; }" : "=r"(a) : "l"(p));
    return a;
}
__device__ __forceinline__ void cp_async16s(uint32_t dst, const void* src) {
    asm volatile("cp.async.cg.shared.global [%0], [%1], 16;\n" :: "r"(dst), "l"(src));
}
__device__ __forceinline__ void cp_commit() { asm volatile("cp.async.commit_group;\n"); }
template <int N>
__device__ __forceinline__ void cp_wait() { asm volatile("cp.async.wait_group %0;\n" :: "n"(N)); }

__device__ __forceinline__ void ldsm4(uint32_t& r0, uint32_t& r1, uint32_t& r2, uint32_t& r3,
                                      uint32_t addr) {
    asm volatile("ldmatrix.sync.aligned.m8n8.x4.shared.b16 {%0,%1,%2,%3}, [%4];\n"
                 : "=r"(r0), "=r"(r1), "=r"(r2), "=r"(r3) : "r"(addr));
}
// fp8 e4m3 mma: m16n8k32, fp32 accum
__device__ __forceinline__ void mma_fp8(float* c, const uint32_t* a, uint32_t b0, uint32_t b1) {
    asm volatile(
        "mma.sync.aligned.m16n8k32.row.col.f32.e4m3.e4m3.f32 "
        "{%0,%1,%2,%3}, {%4,%5,%6,%7}, {%8,%9}, {%0,%1,%2,%3};\n"
        : "+f"(c[0]), "+f"(c[1]), "+f"(c[2]), "+f"(c[3])
        : "r"(a[0]), "r"(a[1]), "r"(a[2]), "r"(a[3]), "r"(b0), "r"(b1));
}

// ---------------- K0: zero accumulators (every launch) ----------------
__global__ void k_zero() {
    int i = blockIdx.x * blockDim.x + threadIdx.x;
    if (i < NN) { g_colsum[i] = 0.f; g_sumsq[i] = 0.f; g_rowsum[i] = 0.f; }
}

// ---------------- K1b: inverse norms (fp32, from original data) ----------------
__global__ void k_invn() {
    int i = blockIdx.x * blockDim.x + threadIdx.x;
    if (i < NN) g_invn[i] = rsqrtf(fmaxf(g_sumsq[i], 1e-30f));
}

// ---------------- K2: transpose + e4m3 convert + fused column stats ----------------
__global__ void k_transpose(const float* __restrict__ qi, const float* __restrict__ qj) {
    __shared__ float tile[32][33];
    __shared__ float s_s[8][32];
    __shared__ float s_s2[8][32];
    int b0 = blockIdx.x * 32;
    int r0 = blockIdx.y * 32;
    const float* q = (r0 < CLS) ? qi : qj;
    int c0 = (r0 < CLS) ? r0 : (r0 - CLS);
    int tx = threadIdx.x, ty = threadIdx.y;

    float s = 0.f, s2 = 0.f;
#pragma unroll
    for (int i = 0; i < 4; ++i) {
        int b = b0 + ty + i * 8;
        float v = q[(size_t)b * CLS + c0 + tx];
        tile[ty + i * 8][tx] = v;
        s += v; s2 += v * v;
    }
    s_s[ty][tx] = s;
    s_s2[ty][tx] = s2;
    __syncthreads();
#pragma unroll
    for (int i = 0; i < 4; ++i) {
        int r = r0 + ty + i * 8;
        int b = b0 + tx;
        g_Xf[(size_t)r * BATCH + b] =
            __nv_cvt_float_to_fp8(tile[tx][ty + i * 8], __NV_SATFINITE, __NV_E4M3);
    }
    if (ty == 0) {
        float ts = 0.f, ts2 = 0.f;
#pragma unroll
        for (int w = 0; w < 8; ++w) { ts += s_s[w][tx]; ts2 += s_s2[w][tx]; }
        atomicAdd(&g_colsum[r0 + tx], ts);
        atomicAdd(&g_sumsq[r0 + tx], ts2);
    }
}

// ---------------- K3: fp8 GEMM (256 thr, 32x64 warp tiles), fused epilogue ----------------
__global__ void __launch_bounds__(256, 2) k_gemm() {
    extern __shared__ __align__(128) uint8_t smem[];
    const uint32_t smem_base = smem_u32(smem);
    const int tid = threadIdx.x;
    const int lane = tid & 31;
    const int warp = tid >> 5;
    const int wm = warp >> 1;   // 0..3 (32 rows each)
    const int wn = warp & 1;    // 0..1 (64 cols each)

    // triangular tile decode: blockIdx.x -> (bi <= bj)
    int t = blockIdx.x;
    int u = (NTRI - 1) - t;
    int k = (int)((sqrtf((float)(8 * u + 1)) - 1.0f) * 0.5f);
    while (k * (k + 1) / 2 > u) --k;
    while ((k + 1) * (k + 2) / 2 <= u) ++k;
    const int bi = (NT1D - 1) - k;
    const int bj = (NT1D - 1) - (u - k * (k + 1) / 2);
    const int M0 = bi * TM;
    const int C0 = bj * TN;
    const bool diag = (bi == bj);
    const bool ptile = (bj == bi + (CLS / TM));   // partner-diagonal block

    // ---- per-thread cp.async plumbing: 4 chunks of 16B per stage-issue ----
    const uint8_t* srcp[4];
    uint32_t dstoff[4];
#pragma unroll
    for (int i = 0; i < 4; ++i) {
        int c = i * 256 + tid;       // 0..1023 ; 0..511 -> A, 512..1023 -> B
        int isB = c >> 9;
        int cc = c & 511;
        int row = cc >> 2;
        int j = cc & 3;
        srcp[i] = g_Xf + (size_t)((isB ? C0 : M0) + row) * BATCH + j * 16;
        dstoff[i] = (isB ? (uint32_t)A_STAGE : 0u) + (uint32_t)(row * PITCHB + j * 16);
    }

    float acc[2][8][4];
#pragma unroll
    for (int mt = 0; mt < 2; ++mt)
#pragma unroll
        for (int nt = 0; nt < 8; ++nt)
#pragma unroll
            for (int v = 0; v < 4; ++v) acc[mt][nt][v] = 0.f;

    // per-lane ldsm base offsets (byte units, stage 0)
    const uint32_t a_off = smem_base +
        (uint32_t)((wm * 32 + (lane & 15)) * PITCHB + (lane >> 4) * 16);
    const uint32_t b_off = smem_base + (uint32_t)A_STAGE +
        (uint32_t)((wn * 64 + ((lane >> 4) & 1) * 8 + (lane & 7)) * PITCHB +
                   ((lane >> 3) & 1) * 16);

    // ---- prologue: stages 0..2 ----
#pragma unroll
    for (int s = 0; s < STAGES - 1; ++s) {
        uint32_t db = smem_base + s * STAGE_BYTES;
#pragma unroll
        for (int i = 0; i < 4; ++i) {
            cp_async16s(db + dstoff[i], srcp[i]);
            srcp[i] += BK;
        }
        cp_commit();
    }

#define COMPUTE_STAGE(S)                                                          \
    do {                                                                          \
        const uint32_t aB = a_off + (uint32_t)((S) * STAGE_BYTES);                \
        const uint32_t bB = b_off + (uint32_t)((S) * STAGE_BYTES);                \
        _Pragma("unroll")                                                         \
        for (int ks = 0; ks < 2; ++ks) {                                          \
            uint32_t a[2][4];                                                     \
            _Pragma("unroll")                                                     \
            for (int mt = 0; mt < 2; ++mt)                                        \
                ldsm4(a[mt][0], a[mt][1], a[mt][2], a[mt][3],                     \
                      aB + (uint32_t)(mt * 16 * PITCHB + ks * 32));               \
            uint32_t b[4][4];                                                     \
            _Pragma("unroll")                                                     \
            for (int i = 0; i < 4; ++i)                                           \
                ldsm4(b[i][0], b[i][1], b[i][2], b[i][3],                         \
                      bB + (uint32_t)(i * 16 * PITCHB + ks * 32));                \
            _Pragma("unroll")                                                     \
            for (int mt = 0; mt < 2; ++mt)                                        \
                _Pragma("unroll")                                                 \
                for (int nt = 0; nt < 8; ++nt)                                    \
                    mma_fp8(acc[mt][nt], a[mt],                                   \
                            b[nt >> 1][(nt & 1) * 2], b[nt >> 1][(nt & 1) * 2 + 1]); \
        }                                                                         \
    } while (0)

#define ISSUE_STAGE(SLOT)                                                         \
    do {                                                                          \
        uint32_t db = smem_base + (uint32_t)((SLOT) * STAGE_BYTES);               \
        _Pragma("unroll")                                                         \
        for (int i = 0; i < 4; ++i) {                                             \
            cp_async16s(db + dstoff[i], srcp[i]);                                 \
            srcp[i] += BK;                                                        \
        }                                                                         \
        cp_commit();                                                              \
    } while (0)

    // ---- main pipeline: it = 0..251, fully constant stage indices ----
    for (int ib = 0; ib < 63; ++ib) {
#pragma unroll
        for (int s = 0; s < 4; ++s) {
            cp_wait<2>();
            __syncthreads();
            ISSUE_STAGE((s + 3) & 3);
            COMPUTE_STAGE(s);
        }
    }
    // ---- tail: it = 252..255 ----
    cp_wait<2>(); __syncthreads(); ISSUE_STAGE(3); COMPUTE_STAGE(0);
    cp_wait<2>(); __syncthreads();                 COMPUTE_STAGE(1);
    cp_wait<1>(); __syncthreads();                 COMPUTE_STAGE(2);
    cp_wait<0>(); __syncthreads();                 COMPUTE_STAGE(3);

#undef COMPUTE_STAGE
#undef ISSUE_STAGE

    // ---------- fused epilogue ----------
    __syncthreads();
    float* s_inv = (float*)smem;      // [0..127]=row invn, [128..255]=col invn
    s_inv[tid] = (tid < 128) ? g_invn[M0 + tid] : g_invn[C0 + tid - 128];
    __syncthreads();

    const int r_loc0 = wm * 32 + (lane >> 2);
    const int c_loc0 = wn * 64 + (lane & 3) * 2;
    float csum[8][2];
#pragma unroll
    for (int nt = 0; nt < 8; ++nt) { csum[nt][0] = 0.f; csum[nt][1] = 0.f; }

#pragma unroll
    for (int mt = 0; mt < 2; ++mt) {
        const int rA = r_loc0 + mt * 16;
        const int rB = rA + 8;
        const float invA = s_inv[rA], invB = s_inv[rB];
        float sA = 0.f, sB = 0.f;
#pragma unroll
        for (int nt = 0; nt < 8; ++nt) {
            const int c0l = c_loc0 + nt * 8;
            const float ic0 = s_inv[128 + c0l], ic1 = s_inv[128 + c0l + 1];
            const float simA0 = acc[mt][nt][0] * invA * ic0;
            const float simA1 = acc[mt][nt][1] * invA * ic1;
            const float simB0 = acc[mt][nt][2] * invB * ic0;
            const float simB1 = acc[mt][nt][3] * invB * ic1;
            if (ptile) {   // partner: global col == global row + CLS  <=> same local idx
                if (rA == c0l)     { g_pos[M0 + rA] = simA0; g_pos[C0 + c0l] = simA0; }
                if (rA == c0l + 1) { g_pos[M0 + rA] = simA1; g_pos[C0 + c0l + 1] = simA1; }
                if (rB == c0l)     { g_pos[M0 + rB] = simB0; g_pos[C0 + c0l] = simB0; }
                if (rB == c0l + 1) { g_pos[M0 + rB] = simB1; g_pos[C0 + c0l + 1] = simB1; }
            }
            float eA0 = __expf(simA0), eA1 = __expf(simA1);
            float eB0 = __expf(simB0), eB1 = __expf(simB1);
            if (diag) {   // exclude self
                if (rA == c0l)     eA0 = 0.f;
                if (rA == c0l + 1) eA1 = 0.f;
                if (rB == c0l)     eB0 = 0.f;
                if (rB == c0l + 1) eB1 = 0.f;
            }
            sA += eA0 + eA1;
            sB += eB0 + eB1;
            if (!diag) {   // symmetric: same values feed the transposed rows
                csum[nt][0] += eA0 + eB0;
                csum[nt][1] += eA1 + eB1;
            }
        }
        sA += __shfl_xor_sync(0xffffffffu, sA, 1);
        sA += __shfl_xor_sync(0xffffffffu, sA, 2);
        sB += __shfl_xor_sync(0xffffffffu, sB, 1);
        sB += __shfl_xor_sync(0xffffffffu, sB, 2);
        if ((lane & 3) == 0) {
            atomicAdd(&g_rowsum[M0 + rA], sA);
            atomicAdd(&g_rowsum[M0 + rB], sB);
        }
    }
    if (!diag) {
#pragma unroll
        for (int nt = 0; nt < 8; ++nt)
#pragma unroll
            for (int v = 0; v < 2; ++v) {
                float x = csum[nt][v];
                x += __shfl_xor_sync(0xffffffffu, x, 4);
                x += __shfl_xor_sync(0xffffffffu, x, 8);
                x += __shfl_xor_sync(0xffffffffu, x, 16);
                if (lane < 4)
                    atomicAdd(&g_rowsum[C0 + wn * 64 + nt * 8 + lane * 2 + v], x);
            }
    }
}

// ---------------- K5: entropy + ce combine ----------------
__global__ void k_final(float* out) {
    __shared__ double sC[256], sTi[256], sSi[256], sTj[256], sSj[256];
    int t = threadIdx.x;
    double ce = 0.0;
    for (int r = t; r < NN; r += 256)
        ce += (double)logf(g_rowsum[r]) - (double)g_pos[r];
    double Ti = 0, Si = 0, Tj = 0, Sj = 0;
    for (int c = t; c < CLS; c += 256) {
        double v = (double)g_colsum[c];
        Ti += v; Si += v * log(v);
        double w = (double)g_colsum[c + CLS];
        Tj += w; Sj += w * log(w);
    }
    sC[t] = ce; sTi[t] = Ti; sSi[t] = Si; sTj[t] = Tj; sSj[t] = Sj;
    __syncthreads();
#pragma unroll
    for (int off = 128; off > 0; off >>= 1) {
        if (t < off) {
            sC[t] += sC[t + off];
            sTi[t] += sTi[t + off]; sSi[t] += sSi[t + off];
            sTj[t] += sTj[t + off]; sSj[t] += sSj[t + off];
        }
        __syncthreads();
    }
    if (t == 0) {
        double nei = log((double)CLS) - log(sTi[0]) + sSi[0] / sTi[0];
        double nej = log((double)CLS) - log(sTj[0]) + sSj[0] / sTj[0];
        out[0] = (float)(sC[0] / (double)NN + nei + nej);
    }
}

// ---------------- launch ----------------
extern "C" void kernel_launch(void* const* d_in, const int* in_sizes, int n_in,
                              void* d_out, int out_size) {
    const float* qi = (const float*)d_in[0];
    const float* qj = (const float*)d_in[1];
    float* out = (float*)d_out;

    cudaFuncSetAttribute(k_gemm, cudaFuncAttributeMaxDynamicSharedMemorySize, SMEM_BYTES);

    k_zero<<<NN / 256, 256>>>();
    k_transpose<<<dim3(BATCH / 32, NN / 32), dim3(32, 8)>>>(qi, qj);
    k_invn<<<NN / 256, 256>>>();
    k_gemm<<<NTRI, 256, SMEM_BYTES>>>();
    k_final<<<1, 256>>>(out);
}